// round 13
// baseline (speedup 1.0000x reference)
#include <cuda_runtime.h>
#include <cuda_fp16.h>
#include <cstdint>

// ---------------------------------------------------------------------------
// Problem constants
// ---------------------------------------------------------------------------
#define BW_   2048
#define NTOK  49
#define NH_   12
#define HD_   32
#define DIM_  384
#define M_    (BW_ * NTOK)   // 100352
#define K_    DIM_

// fp16 scratch (device globals; allocation in kernel_launch is forbidden)
__device__ __align__(16) __half g_xh[M_ * DIM_];
__device__ __align__(16) __half g_wh[4 * DIM_ * DIM_];   // qkv_w then proj_w
__device__ __align__(16) __half g_Qh[BW_ * NH_ * NTOK * HD_];
__device__ __align__(16) __half g_Kh[BW_ * NH_ * NTOK * HD_];
__device__ __align__(16) __half g_Vh[BW_ * NH_ * NTOK * HD_];
__device__ __align__(16) __half g_AOh[M_ * DIM_];

// ---------------------------------------------------------------------------
// helpers
// ---------------------------------------------------------------------------
__device__ __forceinline__ uint32_t smem_u32(const void* p) {
    uint32_t a;
    asm("{ .reg .u64 t; cvta.to.shared.u64 t, %1; cvt.u32.u64 %0, t; }"
        : "=r"(a) : "l"(p));
    return a;
}

// 64B-row swizzle (rows of 32 fp16): conflict-free ldsm + 16B stores
__device__ __forceinline__ uint32_t sw_off(int row, int kb) {
    return (uint32_t)(row * 64 + (kb ^ (((row >> 1) & 3) << 4)));
}

__device__ __forceinline__ void ldsm4(uint32_t* r, uint32_t a) {
    asm volatile("ldmatrix.sync.aligned.m8n8.x4.shared.b16 {%0,%1,%2,%3}, [%4];"
                 : "=r"(r[0]), "=r"(r[1]), "=r"(r[2]), "=r"(r[3]) : "r"(a));
}

__device__ __forceinline__ void ldsm4t(uint32_t* r, uint32_t a) {
    asm volatile("ldmatrix.sync.aligned.m8n8.x4.trans.shared.b16 {%0,%1,%2,%3}, [%4];"
                 : "=r"(r[0]), "=r"(r[1]), "=r"(r[2]), "=r"(r[3]) : "r"(a));
}

__device__ __forceinline__ void mma16816(float* c, const uint32_t* a, const uint32_t* b) {
    asm volatile(
        "mma.sync.aligned.m16n8k16.row.col.f32.f16.f16.f32 "
        "{%0,%1,%2,%3}, {%4,%5,%6,%7}, {%8,%9}, {%0,%1,%2,%3};"
        : "+f"(c[0]), "+f"(c[1]), "+f"(c[2]), "+f"(c[3])
        : "r"(a[0]), "r"(a[1]), "r"(a[2]), "r"(a[3]), "r"(b[0]), "r"(b[1]));
}

__device__ __forceinline__ void cp16(uint32_t dst, const void* src) {
    asm volatile("cp.async.cg.shared.global [%0], [%1], 16;" :: "r"(dst), "l"(src));
}
#define CP_COMMIT() asm volatile("cp.async.commit_group;")
#define CP_WAIT(n)  asm volatile("cp.async.wait_group %0;" :: "n"(n))

__device__ __forceinline__ uint32_t h2u(__half2 h) { return *(uint32_t*)&h; }

// ---------------------------------------------------------------------------
// fp32 -> fp16 convert, all three tensors in one launch
// ---------------------------------------------------------------------------
#define N4X ((M_ * DIM_) / 4)
#define N4W ((3 * DIM_ * DIM_) / 4)
#define N4P ((DIM_ * DIM_) / 4)

__global__ void cvt_all(const float4* __restrict__ x,
                        const float4* __restrict__ qw,
                        const float4* __restrict__ pw) {
    int i = blockIdx.x * blockDim.x + threadIdx.x;
    const float4* src;
    __half* dst;
    int j;
    if (i < N4X)                 { src = x;  dst = g_xh;                   j = i; }
    else if (i < N4X + N4W)      { src = qw; dst = g_wh;                   j = i - N4X; }
    else if (i < N4X + N4W + N4P){ src = pw; dst = g_wh + 3 * DIM_ * DIM_; j = i - N4X - N4W; }
    else return;
    float4 f = src[j];
    uint2 u;
    u.x = h2u(__floats2half2_rn(f.x, f.y));
    u.y = h2u(__floats2half2_rn(f.z, f.w));
    *(uint2*)(dst + (size_t)j * 4) = u;
}

// ---------------------------------------------------------------------------
// fp16 GEMM (f32 acc): identical to 503.8us best config
// CTA 128x128x32, 8 warps (4m x 2n), warp tile 32x64, 5-stage cp.async.
// ---------------------------------------------------------------------------
#define BM 128
#define BN 128
#define BK 32
#define KT (K_ / BK)            // 12
#define STAGES 5
#define A_ST (BM * BK * 2)      // 8192 B
#define B_ST (BN * BK * 2)      // 8192 B
#define STG_ (A_ST + B_ST)      // 16384 B
#define GSMEM (STAGES * STG_)   // 81920 B

template <int MODE>
__global__ __launch_bounds__(256, 2)
void gemm_h(const float* __restrict__ bias, float* __restrict__ out) {
    extern __shared__ __align__(16) uint8_t smem[];

    const __half* Ah = (MODE == 0) ? g_xh : g_AOh;
    const __half* Bh = (MODE == 0) ? g_wh : g_wh + 3 * DIM_ * DIM_;

    const int tid  = threadIdx.x;
    const int lane = tid & 31;
    const int wid  = tid >> 5;
    const int wm   = wid & 3;
    const int wn   = wid >> 2;
    const int bm   = blockIdx.y * BM;
    const int bn   = blockIdx.x * BN;

    const int lrow = tid >> 2;
    const int lc   = tid & 3;
    const __half* Asrc = Ah + (size_t)(bm + lrow) * K_ + lc * 8;
    const __half* Bsrc = Bh + (size_t)(bn + lrow) * K_ + lc * 8;
    const uint32_t sw0 = sw_off(lrow, lc * 16);
    const uint32_t sw1 = sw_off(lrow + 64, lc * 16);

    const uint32_t sb = smem_u32(smem);

    const int arow = wm * 32 + (lane & 15);
    const uint32_t akb = ((lane >> 4) & 1) * 16;
    const uint32_t aoff0 = sw_off(arow, akb);
    const uint32_t aoff1 = sw_off(arow + 16, akb);
    const int nrB = (lane & 7) + ((lane >> 4) & 1) * 8;
    const uint32_t bkb = ((lane >> 3) & 1) * 16;
    uint32_t boff[4];
#pragma unroll
    for (int p = 0; p < 4; ++p) boff[p] = sw_off(wn * 64 + p * 16 + nrB, bkb);

    float acc[2][8][4];
#pragma unroll
    for (int mf = 0; mf < 2; ++mf)
#pragma unroll
        for (int f = 0; f < 8; ++f)
#pragma unroll
            for (int e = 0; e < 4; ++e) acc[mf][f][e] = 0.f;

    auto issue = [&](int kt) {
        const uint32_t ab = sb + (kt % STAGES) * STG_;
        const uint32_t bb = ab + A_ST;
        const __half* as = Asrc + kt * BK;
        const __half* bs = Bsrc + kt * BK;
        cp16(ab + sw0, as);
        cp16(ab + sw1, as + (size_t)64 * K_);
        cp16(bb + sw0, bs);
        cp16(bb + sw1, bs + (size_t)64 * K_);
        CP_COMMIT();
    };

    issue(0); issue(1); issue(2); issue(3);

#pragma unroll
    for (int kt = 0; kt < KT; ++kt) {
        if (kt < KT - 3)      { CP_WAIT(3); }
        else if (kt == KT - 3){ CP_WAIT(2); }
        else if (kt == KT - 2){ CP_WAIT(1); }
        else                  { CP_WAIT(0); }
        __syncthreads();
        if (kt + 4 < KT) issue(kt + 4);

        const uint32_t aB = sb + (kt % STAGES) * STG_;
        const uint32_t bB = aB + A_ST;
#pragma unroll
        for (int ks = 0; ks < 2; ++ks) {
            const uint32_t kx = (uint32_t)ks << 5;
            uint32_t af0[4], af1[4];
            ldsm4(af0, aB + (aoff0 ^ kx));
            ldsm4(af1, aB + (aoff1 ^ kx));
#pragma unroll
            for (int p = 0; p < 4; ++p) {
                uint32_t bf[4];
                ldsm4(bf, bB + (boff[p] ^ kx));
                mma16816(acc[0][2 * p],     af0, bf);
                mma16816(acc[0][2 * p + 1], af0, bf + 2);
                mma16816(acc[1][2 * p],     af1, bf);
                mma16816(acc[1][2 * p + 1], af1, bf + 2);
            }
        }
    }

    const int gr = lane >> 2, tg = lane & 3;

    if (MODE == 0) {
        const int which = bn / DIM_;
        const float scl = (which == 0) ? 0.17677669529663687f : 1.0f;
        __half* dst = (which == 0) ? g_Qh : (which == 1) ? g_Kh : g_Vh;
#pragma unroll
        for (int mf = 0; mf < 2; ++mf) {
#pragma unroll
            for (int e = 0; e < 2; ++e) {
                const int row = bm + wm * 32 + mf * 16 + gr + e * 8;
                const int bwin = row / NTOK;
                const int t = row - bwin * NTOK;
#pragma unroll
                for (int f = 0; f < 8; ++f) {
                    const int n = bn + wn * 64 + f * 8 + tg * 2;
                    const int hh = (n - which * DIM_) >> 5;
                    const int cl = n & 31;
                    float v0 = (acc[mf][f][e * 2 + 0] + bias[n + 0]) * scl;
                    float v1 = (acc[mf][f][e * 2 + 1] + bias[n + 1]) * scl;
                    *(__half2*)(dst + ((size_t)(bwin * NH_ + hh) * NTOK + t) * HD_ + cl) =
                        __floats2half2_rn(v0, v1);
                }
            }
        }
    } else {
#pragma unroll
        for (int mf = 0; mf < 2; ++mf) {
#pragma unroll
            for (int e = 0; e < 2; ++e) {
                const int row = bm + wm * 32 + mf * 16 + gr + e * 8;
#pragma unroll
                for (int f = 0; f < 8; ++f) {
                    const int n = bn + wn * 64 + f * 8 + tg * 2;
                    float2 w;
                    w.x = acc[mf][f][e * 2 + 0] + bias[n + 0];
                    w.y = acc[mf][f][e * 2 + 1] + bias[n + 1];
                    *(float2*)(out + (size_t)row * DIM_ + n) = w;
                }
            }
        }
    }
}

// ---------------------------------------------------------------------------
// Tensorized window attention, pipelined:
// 256-thr CTA = 2 half-CTA slots; each slot processes NITER consecutive
// (window,head) pairs with 2-stage double-buffered cp.async (load pair i+1
// while computing pair i). Dynamic smem 48KB.
// ---------------------------------------------------------------------------
#define APAIRS 2
#define NITER  4
#define PAIR_BUF 12288                 // Q(4096)+K(4096)+V(4096) bytes
#define SLOT_STRIDE (2 * PAIR_BUF)     // 2 stages
#define ASMEM (APAIRS * SLOT_STRIDE)   // 49152 B

__global__ __launch_bounds__(256)
void attn_tc(const float* __restrict__ table) {
    extern __shared__ __align__(16) uint8_t asmem[];
    __shared__ float sbias[APAIRS][169];

    const int tid  = threadIdx.x;
    const int hp   = tid >> 7;        // slot
    const int wtid = tid & 127;
    const int lane = tid & 31;
    const int w    = (wtid >> 5);     // warp within slot (0..3)

    const int pb = blockIdx.x * (APAIRS * NITER) + hp * NITER;  // first pair

    const uint32_t slotb = smem_u32(asmem) + hp * SLOT_STRIDE;
    const int gr = lane >> 2, tg = lane & 3;

    // zero V pad rows 49..63 in both stages (15 rows x 4 chunks = 60)
    if (wtid < 120) {
        const int stg = wtid / 60;
        const int m = wtid - stg * 60;
        const int row = 49 + (m >> 2);
        const uint32_t so = sw_off(row, (m & 3) * 16);
        *(uint4*)((char*)asmem + hp * SLOT_STRIDE + stg * PAIR_BUF + 8192 + so) =
            make_uint4(0, 0, 0, 0);
    }

    auto issueQKV = [&](int stg, int pr) {
        const __half* qg = g_Qh + (size_t)pr * NTOK * HD_;
        const __half* kg = g_Kh + (size_t)pr * NTOK * HD_;
        const __half* vg = g_Vh + (size_t)pr * NTOK * HD_;
        const uint32_t base = slotb + stg * PAIR_BUF;
#pragma unroll
        for (int i = wtid; i < 196; i += 128) {
            const int row = i >> 2, cb = (i & 3) * 16;
            const uint32_t so = sw_off(row, cb);
            const size_t go = (size_t)row * HD_ + (i & 3) * 8;
            cp16(base + so, qg + go);
            cp16(base + 4096 + so, kg + go);
            cp16(base + 8192 + so, vg + go);
        }
        CP_COMMIT();
    };

    // fragment offsets (shared by all iterations)
    const uint32_t aoff = sw_off(w * 16 + (lane & 15), ((lane >> 4) & 1) * 16);
    const int nrB = (lane & 7) + ((lane >> 4) & 1) * 8;
    const uint32_t bkb = ((lane >> 3) & 1) * 16;
    const int vrl   = ((lane >> 3) & 1) * 8 + (lane & 7);
    const int vcsel = (lane >> 4) * 16;
    const int r0 = w * 16 + gr, r1 = r0 + 8;
    const int r0d = r0 / 7, r0m = r0 - r0d * 7;
    const int r1d = r1 / 7, r1m = r1 - r1d * 7;

    issueQKV(0, pb);

    for (int it = 0; it < NITER; ++it) {
        if (it + 1 < NITER) issueQKV((it + 1) & 1, pb + it + 1);

        const int pair = pb + it;
        const int bw = pair / NH_;
        const int h  = pair - bw * NH_;

        // bias column for current pair (L1-hot after first CTAs)
        for (int i = wtid; i < 169; i += 128) sbias[hp][i] = table[i * NH_ + h];

        if (it + 1 < NITER) { CP_WAIT(1); } else { CP_WAIT(0); }
        __syncthreads();

        const uint32_t sQb = slotb + (it & 1) * PAIR_BUF;
        const uint32_t sKb = sQb + 4096;
        const uint32_t sVb = sQb + 8192;

        // ---- S = Q K^T
        float sacc[8][4];
#pragma unroll
        for (int f = 0; f < 8; ++f)
#pragma unroll
            for (int e = 0; e < 4; ++e) sacc[f][e] = 0.f;

#pragma unroll
        for (int ks = 0; ks < 2; ++ks) {
            const uint32_t kx = ks * 32;
            uint32_t af[4];
            ldsm4(af, sQb + (aoff ^ kx));
#pragma unroll
            for (int p = 0; p < 4; ++p) {
                uint32_t bf[4];
                ldsm4(bf, sKb + (sw_off(p * 16 + nrB, bkb) ^ kx));
                mma16816(sacc[2 * p],     af, bf);
                mma16816(sacc[2 * p + 1], af, bf + 2);
            }
        }

        // ---- bias + mask + softmax
        float mx0 = -1e30f, mx1 = -1e30f;
#pragma unroll
        for (int f = 0; f < 8; ++f) {
#pragma unroll
            for (int c = 0; c < 2; ++c) {
                const int j = f * 8 + tg * 2 + c;
                const int jd = j / 7, jm = j - jd * 7;
                const bool jv = (j < NTOK);
                float s0 = -1e30f, s1 = -1e30f;
                if (jv) {
                    float b0 = (r0 < NTOK) ? sbias[hp][(r0d - jd + 6) * 13 + (r0m - jm + 6)] : 0.f;
                    float b1 = (r1 < NTOK) ? sbias[hp][(r1d - jd + 6) * 13 + (r1m - jm + 6)] : 0.f;
                    s0 = sacc[f][c]     + b0;
                    s1 = sacc[f][c + 2] + b1;
                }
                sacc[f][c]     = s0;
                sacc[f][c + 2] = s1;
                mx0 = fmaxf(mx0, s0);
                mx1 = fmaxf(mx1, s1);
            }
        }
        mx0 = fmaxf(mx0, __shfl_xor_sync(0xffffffffu, mx0, 1));
        mx0 = fmaxf(mx0, __shfl_xor_sync(0xffffffffu, mx0, 2));
        mx1 = fmaxf(mx1, __shfl_xor_sync(0xffffffffu, mx1, 1));
        mx1 = fmaxf(mx1, __shfl_xor_sync(0xffffffffu, mx1, 2));

        float sum0 = 0.f, sum1 = 0.f;
#pragma unroll
        for (int f = 0; f < 8; ++f) {
            float e0 = __expf(sacc[f][0] - mx0);
            float e1 = __expf(sacc[f][1] - mx0);
            float e2 = __expf(sacc[f][2] - mx1);
            float e3 = __expf(sacc[f][3] - mx1);
            sacc[f][0] = e0; sacc[f][1] = e1; sacc[f][2] = e2; sacc[f][3] = e3;
            sum0 += e0 + e1;
            sum1 += e2 + e3;
        }
        sum0 += __shfl_xor_sync(0xffffffffu, sum0, 1);
        sum0 += __shfl_xor_sync(0xffffffffu, sum0, 2);
        sum1 += __shfl_xor_sync(0xffffffffu, sum1, 1);
        sum1 += __shfl_xor_sync(0xffffffffu, sum1, 2);
        const float inv0 = __frcp_rn(sum0);
        const float inv1 = __frcp_rn(sum1);

        // ---- P -> A fragments
        uint32_t pa[4][4];
#pragma unroll
        for (int ks = 0; ks < 4; ++ks) {
            pa[ks][0] = h2u(__floats2half2_rn(sacc[2 * ks][0],     sacc[2 * ks][1]));
            pa[ks][1] = h2u(__floats2half2_rn(sacc[2 * ks][2],     sacc[2 * ks][3]));
            pa[ks][2] = h2u(__floats2half2_rn(sacc[2 * ks + 1][0], sacc[2 * ks + 1][1]));
            pa[ks][3] = h2u(__floats2half2_rn(sacc[2 * ks + 1][2], sacc[2 * ks + 1][3]));
        }

        // ---- O = P V via ldmatrix.trans on row-major V
        float oacc[4][4];
#pragma unroll
        for (int f = 0; f < 4; ++f)
#pragma unroll
            for (int e = 0; e < 4; ++e) oacc[f][e] = 0.f;

#pragma unroll
        for (int ks = 0; ks < 4; ++ks) {
#pragma unroll
            for (int p = 0; p < 2; ++p) {
                uint32_t bf[4];
                ldsm4t(bf, sVb + sw_off(ks * 16 + vrl, p * 32 + vcsel));
                mma16816(oacc[2 * p],     pa[ks], bf);
                mma16816(oacc[2 * p + 1], pa[ks], bf + 2);
            }
        }

        if (r0 < NTOK) {
            __half* o = g_AOh + ((size_t)bw * NTOK + r0) * DIM_ + h * HD_;
#pragma unroll
            for (int f = 0; f < 4; ++f) {
                const int d = f * 8 + tg * 2;
                *(__half2*)(o + d) =
                    __floats2half2_rn(oacc[f][0] * inv0, oacc[f][1] * inv0);
            }
        }
        if (r1 < NTOK) {
            __half* o = g_AOh + ((size_t)bw * NTOK + r1) * DIM_ + h * HD_;
#pragma unroll
            for (int f = 0; f < 4; ++f) {
                const int d = f * 8 + tg * 2;
                *(__half2*)(o + d) =
                    __floats2half2_rn(oacc[f][2] * inv1, oacc[f][3] * inv1);
            }
        }

        __syncthreads();   // protect stage buffers before next issue
    }
}

// ---------------------------------------------------------------------------
extern "C" void kernel_launch(void* const* d_in, const int* in_sizes, int n_in,
                              void* d_out, int out_size) {
    const float* x      = (const float*)d_in[0];
    const float* qkv_w  = (const float*)d_in[1];
    const float* qkv_b  = (const float*)d_in[2];
    const float* proj_w = (const float*)d_in[3];
    const float* proj_b = (const float*)d_in[4];
    const float* table  = (const float*)d_in[5];
    float* out = (float*)d_out;

    cudaFuncSetAttribute(gemm_h<0>, cudaFuncAttributeMaxDynamicSharedMemorySize, GSMEM);
    cudaFuncSetAttribute(gemm_h<1>, cudaFuncAttributeMaxDynamicSharedMemorySize, GSMEM);
    cudaFuncSetAttribute(attn_tc,   cudaFuncAttributeMaxDynamicSharedMemorySize, ASMEM);

    const int n4 = N4X + N4W + N4P;
    cvt_all<<<(n4 + 255) / 256, 256>>>((const float4*)x, (const float4*)qkv_w,
                                       (const float4*)proj_w);

    gemm_h<0><<<dim3((3 * DIM_) / BN, M_ / BM), 256, GSMEM>>>(qkv_b, nullptr);

    attn_tc<<<(BW_ * NH_) / (APAIRS * NITER), 256, ASMEM>>>(table);

    gemm_h<1><<<dim3(DIM_ / BN, M_ / BM), 256, GSMEM>>>(proj_b, out);
}

// round 15
// speedup vs baseline: 1.0804x; 1.0804x over previous
#include <cuda_runtime.h>
#include <cuda_fp16.h>
#include <cstdint>

// ---------------------------------------------------------------------------
// Problem constants
// ---------------------------------------------------------------------------
#define BW_   2048
#define NTOK  49
#define NH_   12
#define HD_   32
#define DIM_  384
#define M_    (BW_ * NTOK)   // 100352
#define K_    DIM_

// fp16 scratch (device globals; allocation in kernel_launch is forbidden)
__device__ __align__(16) __half g_xh[M_ * DIM_];
__device__ __align__(16) __half g_wh[4 * DIM_ * DIM_];   // qkv_w then proj_w
__device__ __align__(16) __half g_Qh[BW_ * NH_ * NTOK * HD_];
__device__ __align__(16) __half g_Kh[BW_ * NH_ * NTOK * HD_];
__device__ __align__(16) __half g_Vh[BW_ * NH_ * NTOK * HD_];
__device__ __align__(16) __half g_AOh[M_ * DIM_];

// ---------------------------------------------------------------------------
// helpers
// ---------------------------------------------------------------------------
__device__ __forceinline__ uint32_t smem_u32(const void* p) {
    uint32_t a;
    asm("{ .reg .u64 t; cvta.to.shared.u64 t, %1; cvt.u32.u64 %0, t; }"
        : "=r"(a) : "l"(p));
    return a;
}

// 64B-row swizzle (rows of 32 fp16): conflict-free ldsm + 16B stores
__device__ __forceinline__ uint32_t sw_off(int row, int kb) {
    return (uint32_t)(row * 64 + (kb ^ (((row >> 1) & 3) << 4)));
}

__device__ __forceinline__ void ldsm4(uint32_t* r, uint32_t a) {
    asm volatile("ldmatrix.sync.aligned.m8n8.x4.shared.b16 {%0,%1,%2,%3}, [%4];"
                 : "=r"(r[0]), "=r"(r[1]), "=r"(r[2]), "=r"(r[3]) : "r"(a));
}

__device__ __forceinline__ void ldsm4t(uint32_t* r, uint32_t a) {
    asm volatile("ldmatrix.sync.aligned.m8n8.x4.trans.shared.b16 {%0,%1,%2,%3}, [%4];"
                 : "=r"(r[0]), "=r"(r[1]), "=r"(r[2]), "=r"(r[3]) : "r"(a));
}

__device__ __forceinline__ void mma16816(float* c, const uint32_t* a, const uint32_t* b) {
    asm volatile(
        "mma.sync.aligned.m16n8k16.row.col.f32.f16.f16.f32 "
        "{%0,%1,%2,%3}, {%4,%5,%6,%7}, {%8,%9}, {%0,%1,%2,%3};"
        : "+f"(c[0]), "+f"(c[1]), "+f"(c[2]), "+f"(c[3])
        : "r"(a[0]), "r"(a[1]), "r"(a[2]), "r"(a[3]), "r"(b[0]), "r"(b[1]));
}

__device__ __forceinline__ void cp16(uint32_t dst, const void* src) {
    asm volatile("cp.async.cg.shared.global [%0], [%1], 16;" :: "r"(dst), "l"(src));
}
#define CP_COMMIT() asm volatile("cp.async.commit_group;")
#define CP_WAIT(n)  asm volatile("cp.async.wait_group %0;" :: "n"(n))

__device__ __forceinline__ uint32_t h2u(__half2 h) { return *(uint32_t*)&h; }

// ---------------------------------------------------------------------------
// fp32 -> fp16 convert, all three tensors in one launch
// ---------------------------------------------------------------------------
#define N4X ((M_ * DIM_) / 4)
#define N4W ((3 * DIM_ * DIM_) / 4)
#define N4P ((DIM_ * DIM_) / 4)

__global__ void cvt_all(const float4* __restrict__ x,
                        const float4* __restrict__ qw,
                        const float4* __restrict__ pw) {
    int i = blockIdx.x * blockDim.x + threadIdx.x;
    const float4* src;
    __half* dst;
    int j;
    if (i < N4X)                 { src = x;  dst = g_xh;                   j = i; }
    else if (i < N4X + N4W)      { src = qw; dst = g_wh;                   j = i - N4X; }
    else if (i < N4X + N4W + N4P){ src = pw; dst = g_wh + 3 * DIM_ * DIM_; j = i - N4X - N4W; }
    else return;
    float4 f = src[j];
    uint2 u;
    u.x = h2u(__floats2half2_rn(f.x, f.y));
    u.y = h2u(__floats2half2_rn(f.z, f.w));
    *(uint2*)(dst + (size_t)j * 4) = u;
}

// ---------------------------------------------------------------------------
// fp16 GEMM (f32 acc): C[M,N] = A[M,K] * B[N,K]^T (+bias)
// MODE 0: A = g_xh, B = qkv weights, N=1152, epilogue -> fp16 Q/K/V scatter
// MODE 1: A = g_AOh, B = proj weights, N=384, epilogue -> fp32 out
// CTA 128x128x32, 4 warps (2m x 2n), warp tile 64x64 (ldsm/MMA = 0.25),
// 4-stage cp.async, 128 threads, 2 CTAs/SM. B-fragments consumed
// immediately after load to cap live registers (~180).
// ---------------------------------------------------------------------------
#define BM 128
#define BN 128
#define BK 32
#define KT (K_ / BK)            // 12
#define STAGES 4
#define A_ST (BM * BK * 2)      // 8192 B
#define B_ST (BN * BK * 2)      // 8192 B
#define STG_ (A_ST + B_ST)      // 16384 B
#define GSMEM (STAGES * STG_)   // 65536 B

template <int MODE>
__global__ __launch_bounds__(128, 2)
void gemm_h(const float* __restrict__ bias, float* __restrict__ out) {
    extern __shared__ __align__(16) uint8_t smem[];

    const __half* Ah = (MODE == 0) ? g_xh : g_AOh;
    const __half* Bh = (MODE == 0) ? g_wh : g_wh + 3 * DIM_ * DIM_;

    const int tid  = threadIdx.x;
    const int lane = tid & 31;
    const int wid  = tid >> 5;
    const int wm   = wid & 1;     // 2 warps along m (64 each)
    const int wn   = wid >> 1;    // 2 warps along n (64 each)
    const int bm   = blockIdx.y * BM;
    const int bn   = blockIdx.x * BN;

    // loader: 128 threads; row = tid>>2 (+j*32), 16B chunk col = tid&3
    const int lrow = tid >> 2;
    const int lc   = tid & 3;
    const __half* Asrc = Ah + (size_t)(bm + lrow) * K_ + lc * 8;
    const __half* Bsrc = Bh + (size_t)(bn + lrow) * K_ + lc * 8;
    uint32_t swst[4];
#pragma unroll
    for (int j = 0; j < 4; ++j) swst[j] = sw_off(lrow + j * 32, lc * 16);

    const uint32_t sb = smem_u32(smem);

    // fragment offsets (k-slice ks -> ^ (ks<<5))
    const uint32_t akb = ((lane >> 4) & 1) * 16;
    uint32_t aoff[4];
#pragma unroll
    for (int q = 0; q < 4; ++q)
        aoff[q] = sw_off(wm * 64 + q * 16 + (lane & 15), akb);
    const int nrB = (lane & 7) + ((lane >> 4) & 1) * 8;
    const uint32_t bkb = ((lane >> 3) & 1) * 16;
    uint32_t boff[4];
#pragma unroll
    for (int p = 0; p < 4; ++p) boff[p] = sw_off(wn * 64 + p * 16 + nrB, bkb);

    float acc[4][8][4];
#pragma unroll
    for (int q = 0; q < 4; ++q)
#pragma unroll
        for (int f = 0; f < 8; ++f)
#pragma unroll
            for (int e = 0; e < 4; ++e) acc[q][f][e] = 0.f;

    auto issue = [&](int kt) {
        const uint32_t ab = sb + (kt % STAGES) * STG_;
        const uint32_t bb = ab + A_ST;
        const __half* as = Asrc + kt * BK;
        const __half* bs = Bsrc + kt * BK;
#pragma unroll
        for (int j = 0; j < 4; ++j) {
            cp16(ab + swst[j], as + (size_t)j * 32 * K_);
            cp16(bb + swst[j], bs + (size_t)j * 32 * K_);
        }
        CP_COMMIT();
    };

    issue(0); issue(1); issue(2);

#pragma unroll
    for (int kt = 0; kt < KT; ++kt) {
        if (kt < KT - 2)      { CP_WAIT(2); }
        else if (kt == KT - 2){ CP_WAIT(1); }
        else                  { CP_WAIT(0); }
        __syncthreads();
        if (kt + 3 < KT) issue(kt + 3);

        const uint32_t aB = sb + (kt % STAGES) * STG_;
        const uint32_t bB = aB + A_ST;
#pragma unroll
        for (int ks = 0; ks < 2; ++ks) {
            const uint32_t kx = (uint32_t)ks << 5;
            uint32_t af[4][4];
#pragma unroll
            for (int q = 0; q < 4; ++q) ldsm4(af[q], aB + (aoff[q] ^ kx));
#pragma unroll
            for (int p = 0; p < 4; ++p) {
                uint32_t bf[4];
                ldsm4(bf, bB + (boff[p] ^ kx));
#pragma unroll
                for (int q = 0; q < 4; ++q) {
                    mma16816(acc[q][2 * p],     af[q], bf);
                    mma16816(acc[q][2 * p + 1], af[q], bf + 2);
                }
            }
        }
    }

    // ---- epilogue ----
    const int gr = lane >> 2, tg = lane & 3;

    if (MODE == 0) {
        const int which = bn / DIM_;      // 1152 = 3*384; bn mult of 128 -> uniform
        const float scl = (which == 0) ? 0.17677669529663687f : 1.0f;
        __half* dst = (which == 0) ? g_Qh : (which == 1) ? g_Kh : g_Vh;
#pragma unroll
        for (int q = 0; q < 4; ++q) {
#pragma unroll
            for (int e = 0; e < 2; ++e) {
                const int row = bm + wm * 64 + q * 16 + gr + e * 8;
                const int bwin = row / NTOK;
                const int t = row - bwin * NTOK;
#pragma unroll
                for (int f = 0; f < 8; ++f) {
                    const int n = bn + wn * 64 + f * 8 + tg * 2;
                    const int hh = (n - which * DIM_) >> 5;
                    const int cl = n & 31;
                    float v0 = (acc[q][f][e * 2 + 0] + bias[n + 0]) * scl;
                    float v1 = (acc[q][f][e * 2 + 1] + bias[n + 1]) * scl;
                    *(__half2*)(dst + ((size_t)(bwin * NH_ + hh) * NTOK + t) * HD_ + cl) =
                        __floats2half2_rn(v0, v1);
                }
            }
        }
    } else {
#pragma unroll
        for (int q = 0; q < 4; ++q) {
#pragma unroll
            for (int e = 0; e < 2; ++e) {
                const int row = bm + wm * 64 + q * 16 + gr + e * 8;
#pragma unroll
                for (int f = 0; f < 8; ++f) {
                    const int n = bn + wn * 64 + f * 8 + tg * 2;
                    float2 w;
                    w.x = acc[q][f][e * 2 + 0] + bias[n + 0];
                    w.y = acc[q][f][e * 2 + 1] + bias[n + 1];
                    *(float2*)(out + (size_t)row * DIM_ + n) = w;
                }
            }
        }
    }
}

// ---------------------------------------------------------------------------
// Tensorized window attention (round-11 best): 256-thr CTA = 2 pairs.
// ---------------------------------------------------------------------------
#define APAIRS 2

__global__ __launch_bounds__(256)
void attn_tc(const float* __restrict__ table) {
    __shared__ __align__(16) __half sQ[APAIRS][64 * 32];
    __shared__ __align__(16) __half sK[APAIRS][64 * 32];
    __shared__ __align__(16) __half sV[APAIRS][64 * 32];
    __shared__ float sbias[APAIRS][169];

    const int tid  = threadIdx.x;
    const int hp   = tid >> 7;
    const int wtid = tid & 127;
    const int lane = tid & 31;
    const int w    = (wtid >> 5);

    const int pair = blockIdx.x * APAIRS + hp;
    const int bw   = pair / NH_;
    const int h    = pair - bw * NH_;

    const __half* qg = g_Qh + (size_t)pair * NTOK * HD_;
    const __half* kg = g_Kh + (size_t)pair * NTOK * HD_;
    const __half* vg = g_Vh + (size_t)pair * NTOK * HD_;
    const uint32_t sQb = smem_u32(sQ[hp]);
    const uint32_t sKb = smem_u32(sK[hp]);
    const uint32_t sVb = smem_u32(sV[hp]);

    if (wtid < 60) {
        const int row = 49 + (wtid >> 2);
        *(uint4*)((char*)sV[hp] + sw_off(row, (wtid & 3) * 16)) = make_uint4(0, 0, 0, 0);
    }
    for (int i = wtid; i < 196; i += 128) {
        const int row = i >> 2, cb = (i & 3) * 16;
        const uint32_t so = sw_off(row, cb);
        const size_t go = (size_t)row * HD_ + (i & 3) * 8;
        cp16(sQb + so, qg + go);
        cp16(sKb + so, kg + go);
        cp16(sVb + so, vg + go);
    }
    CP_COMMIT();
    for (int i = wtid; i < 169; i += 128) sbias[hp][i] = table[i * NH_ + h];
    CP_WAIT(0);
    __syncthreads();

    const int gr = lane >> 2, tg = lane & 3;

    float sacc[8][4];
#pragma unroll
    for (int f = 0; f < 8; ++f)
#pragma unroll
        for (int e = 0; e < 4; ++e) sacc[f][e] = 0.f;

    const uint32_t aoff = sw_off(w * 16 + (lane & 15), ((lane >> 4) & 1) * 16);
    const int nrB = (lane & 7) + ((lane >> 4) & 1) * 8;
    const uint32_t bkb = ((lane >> 3) & 1) * 16;
#pragma unroll
    for (int ks = 0; ks < 2; ++ks) {
        const uint32_t kx = ks * 32;
        uint32_t af[4];
        ldsm4(af, sQb + (aoff ^ kx));
#pragma unroll
        for (int p = 0; p < 4; ++p) {
            uint32_t bf[4];
            ldsm4(bf, sKb + (sw_off(p * 16 + nrB, bkb) ^ kx));
            mma16816(sacc[2 * p],     af, bf);
            mma16816(sacc[2 * p + 1], af, bf + 2);
        }
    }

    const int r0 = w * 16 + gr, r1 = r0 + 8;
    const int r0d = r0 / 7, r0m = r0 - r0d * 7;
    const int r1d = r1 / 7, r1m = r1 - r1d * 7;
    float mx0 = -1e30f, mx1 = -1e30f;
#pragma unroll
    for (int f = 0; f < 8; ++f) {
#pragma unroll
        for (int c = 0; c < 2; ++c) {
            const int j = f * 8 + tg * 2 + c;
            const int jd = j / 7, jm = j - jd * 7;
            const bool jv = (j < NTOK);
            float s0 = -1e30f, s1 = -1e30f;
            if (jv) {
                float b0 = (r0 < NTOK) ? sbias[hp][(r0d - jd + 6) * 13 + (r0m - jm + 6)] : 0.f;
                float b1 = (r1 < NTOK) ? sbias[hp][(r1d - jd + 6) * 13 + (r1m - jm + 6)] : 0.f;
                s0 = sacc[f][c]     + b0;
                s1 = sacc[f][c + 2] + b1;
            }
            sacc[f][c]     = s0;
            sacc[f][c + 2] = s1;
            mx0 = fmaxf(mx0, s0);
            mx1 = fmaxf(mx1, s1);
        }
    }
    mx0 = fmaxf(mx0, __shfl_xor_sync(0xffffffffu, mx0, 1));
    mx0 = fmaxf(mx0, __shfl_xor_sync(0xffffffffu, mx0, 2));
    mx1 = fmaxf(mx1, __shfl_xor_sync(0xffffffffu, mx1, 1));
    mx1 = fmaxf(mx1, __shfl_xor_sync(0xffffffffu, mx1, 2));

    float sum0 = 0.f, sum1 = 0.f;
#pragma unroll
    for (int f = 0; f < 8; ++f) {
        float e0 = __expf(sacc[f][0] - mx0);
        float e1 = __expf(sacc[f][1] - mx0);
        float e2 = __expf(sacc[f][2] - mx1);
        float e3 = __expf(sacc[f][3] - mx1);
        sacc[f][0] = e0; sacc[f][1] = e1; sacc[f][2] = e2; sacc[f][3] = e3;
        sum0 += e0 + e1;
        sum1 += e2 + e3;
    }
    sum0 += __shfl_xor_sync(0xffffffffu, sum0, 1);
    sum0 += __shfl_xor_sync(0xffffffffu, sum0, 2);
    sum1 += __shfl_xor_sync(0xffffffffu, sum1, 1);
    sum1 += __shfl_xor_sync(0xffffffffu, sum1, 2);
    const float inv0 = __frcp_rn(sum0);
    const float inv1 = __frcp_rn(sum1);

    uint32_t pa[4][4];
#pragma unroll
    for (int ks = 0; ks < 4; ++ks) {
        pa[ks][0] = h2u(__floats2half2_rn(sacc[2 * ks][0],     sacc[2 * ks][1]));
        pa[ks][1] = h2u(__floats2half2_rn(sacc[2 * ks][2],     sacc[2 * ks][3]));
        pa[ks][2] = h2u(__floats2half2_rn(sacc[2 * ks + 1][0], sacc[2 * ks + 1][1]));
        pa[ks][3] = h2u(__floats2half2_rn(sacc[2 * ks + 1][2], sacc[2 * ks + 1][3]));
    }

    const int vrl   = ((lane >> 3) & 1) * 8 + (lane & 7);
    const int vcsel = (lane >> 4) * 16;

    float oacc[4][4];
#pragma unroll
    for (int f = 0; f < 4; ++f)
#pragma unroll
        for (int e = 0; e < 4; ++e) oacc[f][e] = 0.f;

#pragma unroll
    for (int ks = 0; ks < 4; ++ks) {
#pragma unroll
        for (int p = 0; p < 2; ++p) {
            uint32_t bf[4];
            ldsm4t(bf, sVb + sw_off(ks * 16 + vrl, p * 32 + vcsel));
            mma16816(oacc[2 * p],     pa[ks], bf);
            mma16816(oacc[2 * p + 1], pa[ks], bf + 2);
        }
    }

    if (r0 < NTOK) {
        __half* o = g_AOh + ((size_t)bw * NTOK + r0) * DIM_ + h * HD_;
#pragma unroll
        for (int f = 0; f < 4; ++f) {
            const int d = f * 8 + tg * 2;
            *(__half2*)(o + d) =
                __floats2half2_rn(oacc[f][0] * inv0, oacc[f][1] * inv0);
        }
    }
    if (r1 < NTOK) {
        __half* o = g_AOh + ((size_t)bw * NTOK + r1) * DIM_ + h * HD_;
#pragma unroll
        for (int f = 0; f < 4; ++f) {
            const int d = f * 8 + tg * 2;
            *(__half2*)(o + d) =
                __floats2half2_rn(oacc[f][2] * inv1, oacc[f][3] * inv1);
        }
    }
}

// ---------------------------------------------------------------------------
extern "C" void kernel_launch(void* const* d_in, const int* in_sizes, int n_in,
                              void* d_out, int out_size) {
    const float* x      = (const float*)d_in[0];
    const float* qkv_w  = (const float*)d_in[1];
    const float* qkv_b  = (const float*)d_in[2];
    const float* proj_w = (const float*)d_in[3];
    const float* proj_b = (const float*)d_in[4];
    const float* table  = (const float*)d_in[5];
    float* out = (float*)d_out;

    cudaFuncSetAttribute(gemm_h<0>, cudaFuncAttributeMaxDynamicSharedMemorySize, GSMEM);
    cudaFuncSetAttribute(gemm_h<1>, cudaFuncAttributeMaxDynamicSharedMemorySize, GSMEM);

    const int n4 = N4X + N4W + N4P;
    cvt_all<<<(n4 + 255) / 256, 256>>>((const float4*)x, (const float4*)qkv_w,
                                       (const float4*)proj_w);

    gemm_h<0><<<dim3((3 * DIM_) / BN, M_ / BM), 128, GSMEM>>>(qkv_b, nullptr);

    attn_tc<<<(BW_ * NH_) / APAIRS, 256>>>(table);

    gemm_h<1><<<dim3(DIM_ / BN, M_ / BM), 128, GSMEM>>>(proj_b, out);
}